// round 1
// baseline (speedup 1.0000x reference)
#include <cuda_runtime.h>

#define BATCH 4096
#define FEAT 40960
#define H1 256
#define CAP 2048   // max nonzeros buffered per row (actual data has ~30)

// Scratch (no allocation allowed): transposed feature-transform table + hidden acts
__device__ float g_ftw_t[(size_t)FEAT * H1];     // 42 MB, [feature][h]
__device__ float g_x[(size_t)BATCH * 2 * H1];    // 8 MB,  [row][512] = concat(white, black)

// ---------------------------------------------------------------------------
// Kernel 1: transpose ft_w [256, 40960] -> g_ftw_t [40960, 256]
// ---------------------------------------------------------------------------
__global__ void transpose_kernel(const float* __restrict__ ft_w) {
    __shared__ float tile[32][33];
    int j0 = blockIdx.x * 32;   // feature tile
    int h0 = blockIdx.y * 32;   // hidden tile
    int tx = threadIdx.x, ty = threadIdx.y;
#pragma unroll
    for (int k = 0; k < 4; k++)
        tile[ty + 8 * k][tx] = ft_w[(size_t)(h0 + ty + 8 * k) * FEAT + j0 + tx];
    __syncthreads();
#pragma unroll
    for (int k = 0; k < 4; k++)
        g_ftw_t[(size_t)(j0 + ty + 8 * k) * H1 + h0 + tx] = tile[tx][ty + 8 * k];
}

// ---------------------------------------------------------------------------
// Kernel 2: per (row, side): scan dense row, extract nonzeros, gather-sum
// transposed ft rows, add bias, crelu, write into g_x.
// One block (256 threads) per row per side. blockIdx.y = side (0=white,1=black).
// ---------------------------------------------------------------------------
__global__ void __launch_bounds__(256) ft_kernel(
    const float* __restrict__ wf, const float* __restrict__ bf,
    const float* __restrict__ ft_b)
{
    __shared__ int   s_idx[CAP];
    __shared__ float s_val[CAP];
    __shared__ int   s_count;

    int row  = blockIdx.x;
    int side = blockIdx.y;
    const float* feats = side ? bf : wf;
    const float4* frow = (const float4*)(feats + (size_t)row * FEAT);
    int tid = threadIdx.x;

    if (tid == 0) s_count = 0;
    __syncthreads();

    // Coalesced float4 scan: 10240 float4 / 256 threads = 40 iters
#pragma unroll 4
    for (int i = tid; i < FEAT / 4; i += 256) {
        float4 v = frow[i];
        if (v.x != 0.f) { int p = atomicAdd(&s_count, 1); if (p < CAP) { s_idx[p] = 4 * i;     s_val[p] = v.x; } }
        if (v.y != 0.f) { int p = atomicAdd(&s_count, 1); if (p < CAP) { s_idx[p] = 4 * i + 1; s_val[p] = v.y; } }
        if (v.z != 0.f) { int p = atomicAdd(&s_count, 1); if (p < CAP) { s_idx[p] = 4 * i + 2; s_val[p] = v.z; } }
        if (v.w != 0.f) { int p = atomicAdd(&s_count, 1); if (p < CAP) { s_idx[p] = 4 * i + 3; s_val[p] = v.w; } }
    }
    __syncthreads();

    int n = min(s_count, CAP);
    float acc = ft_b[tid];
    for (int k = 0; k < n; k++) {
        // contiguous 1KB gather per nonzero; L2-resident table
        acc = fmaf(s_val[k], __ldg(&g_ftw_t[(size_t)s_idx[k] * H1 + tid]), acc);
    }
    acc = fminf(fmaxf(acc, 0.f), 1.f);
    g_x[(size_t)row * 512 + side * 256 + tid] = acc;
}

// ---------------------------------------------------------------------------
// Kernel 3: tail MLP. One warp per batch row, 8 rows per 256-thread block.
// y1 = crelu(fc1_w @ x + b1); y2 = crelu(fc2_w @ y1 + b2); out = fc3_w @ y2 + b3
// ---------------------------------------------------------------------------
__global__ void __launch_bounds__(256) mlp_kernel(
    const float* __restrict__ fc1_w, const float* __restrict__ fc1_b,
    const float* __restrict__ fc2_w, const float* __restrict__ fc2_b,
    const float* __restrict__ fc3_w, const float* __restrict__ fc3_b,
    float* __restrict__ out)
{
    __shared__ float fc2t[32 * 32];   // transposed: [j][h] so lane reads are conflict-free
    __shared__ float s_fc3[32];
    int tid = threadIdx.x;

    for (int i = tid; i < 1024; i += 256) {
        int h = i >> 5, j = i & 31;
        fc2t[j * 32 + h] = fc2_w[i];
    }
    if (tid < 32) s_fc3[tid] = fc3_w[tid];
    __syncthreads();

    int warp = tid >> 5, lane = tid & 31;
    int row = blockIdx.x * 8 + warp;

    // Load this row's 512 activations into registers (coalesced)
    const float* xr = g_x + (size_t)row * 512;
    float xv[16];
#pragma unroll
    for (int k = 0; k < 16; k++) xv[k] = xr[lane + 32 * k];

    // fc1: for each output h, partial dot over lanes + butterfly reduce
    float y1 = 0.f;
#pragma unroll
    for (int h = 0; h < 32; h++) {
        const float* w = fc1_w + h * 512;
        float p = 0.f;
#pragma unroll
        for (int k = 0; k < 16; k++) p = fmaf(__ldg(&w[lane + 32 * k]), xv[k], p);
#pragma unroll
        for (int o = 16; o; o >>= 1) p += __shfl_xor_sync(0xffffffffu, p, o);
        p += fc1_b[h];
        p = fminf(fmaxf(p, 0.f), 1.f);
        if (lane == h) y1 = p;    // y1[h] lives in lane h
    }

    // fc2: lane h2 owns output h2; broadcast y1[j] via shfl
    float y2 = fc2_b[lane];
#pragma unroll
    for (int j = 0; j < 32; j++) {
        float xj = __shfl_sync(0xffffffffu, y1, j);
        y2 = fmaf(fc2t[j * 32 + lane], xj, y2);
    }
    y2 = fminf(fmaxf(y2, 0.f), 1.f);

    // fc3: reduce across lanes
    float p3 = s_fc3[lane] * y2;
#pragma unroll
    for (int o = 16; o; o >>= 1) p3 += __shfl_xor_sync(0xffffffffu, p3, o);
    if (lane == 0) out[row] = p3 + fc3_b[0];
}

// ---------------------------------------------------------------------------
extern "C" void kernel_launch(void* const* d_in, const int* in_sizes, int n_in,
                              void* d_out, int out_size) {
    const float* wf    = (const float*)d_in[0];
    const float* bf    = (const float*)d_in[1];
    const float* ft_w  = (const float*)d_in[2];
    const float* ft_b  = (const float*)d_in[3];
    const float* fc1_w = (const float*)d_in[4];
    const float* fc1_b = (const float*)d_in[5];
    const float* fc2_w = (const float*)d_in[6];
    const float* fc2_b = (const float*)d_in[7];
    const float* fc3_w = (const float*)d_in[8];
    const float* fc3_b = (const float*)d_in[9];
    float* out = (float*)d_out;

    dim3 tb(32, 8);
    dim3 tg(FEAT / 32, H1 / 32);
    transpose_kernel<<<tg, tb>>>(ft_w);

    dim3 fg(BATCH, 2);
    ft_kernel<<<fg, 256>>>(wf, bf, ft_b);

    mlp_kernel<<<BATCH / 8, 256>>>(fc1_w, fc1_b, fc2_w, fc2_b, fc3_w, fc3_b, out);
}

// round 3
// speedup vs baseline: 1.0670x; 1.0670x over previous
#include <cuda_runtime.h>

#define BATCH 4096
#define FEAT 40960
#define H1 256
#define CAP 256   // max nonzeros buffered per row (actual data has <=30)

// Scratch (no allocation allowed)
__device__ float g_ftw_t[(size_t)FEAT * H1];     // 42 MB, [feature][h] — keep L2-resident
__device__ float g_x[(size_t)BATCH * 2 * H1];    // 8 MB,  [row][512]

// Streaming float4 load: evict-first in L1+L2 (don't displace the table)
__device__ __forceinline__ float4 ld_stream_f4(const float4* p) {
    float4 v;
    asm volatile("ld.global.cs.v4.f32 {%0,%1,%2,%3}, [%4];"
                 : "=f"(v.x), "=f"(v.y), "=f"(v.z), "=f"(v.w) : "l"(p));
    return v;
}
// Table gather: 32-byte load with L2 evict_last (sticky). Legal form on sm_103.
struct F8 { float f[8]; };
__device__ __forceinline__ F8 ld_table_f8(const float* p) {
    unsigned long long a, b, c, d;
    asm volatile("ld.global.nc.L2::evict_last.v4.b64 {%0,%1,%2,%3}, [%4];"
                 : "=l"(a), "=l"(b), "=l"(c), "=l"(d) : "l"(p));
    F8 r;
    r.f[0] = __uint_as_float((unsigned)a);        r.f[1] = __uint_as_float((unsigned)(a >> 32));
    r.f[2] = __uint_as_float((unsigned)b);        r.f[3] = __uint_as_float((unsigned)(b >> 32));
    r.f[4] = __uint_as_float((unsigned)c);        r.f[5] = __uint_as_float((unsigned)(c >> 32));
    r.f[6] = __uint_as_float((unsigned)d);        r.f[7] = __uint_as_float((unsigned)(d >> 32));
    return r;
}

// ---------------------------------------------------------------------------
// Kernel 1: transpose ft_w [256, 40960] -> g_ftw_t [40960, 256]
// ---------------------------------------------------------------------------
__global__ void transpose_kernel(const float* __restrict__ ft_w) {
    __shared__ float tile[32][33];
    int j0 = blockIdx.x * 32;
    int h0 = blockIdx.y * 32;
    int tx = threadIdx.x, ty = threadIdx.y;
#pragma unroll
    for (int k = 0; k < 4; k++)
        tile[ty + 8 * k][tx] = ft_w[(size_t)(h0 + ty + 8 * k) * FEAT + j0 + tx];
    __syncthreads();
#pragma unroll
    for (int k = 0; k < 4; k++)
        g_ftw_t[(size_t)(j0 + ty + 8 * k) * H1 + h0 + tx] = tile[tx][ty + 8 * k];
}

// ---------------------------------------------------------------------------
// Kernel 2: per (row, side): streaming scan -> nonzero extraction -> warp-
// parallel gather of L2-resident table rows (32B/lane, evict_last) -> smem
// reduction across warps -> bias + crelu -> g_x.
// One block (256 threads = 8 warps) per (row, side).
// ---------------------------------------------------------------------------
__global__ void __launch_bounds__(256) ft_kernel(
    const float* __restrict__ wf, const float* __restrict__ bf,
    const float* __restrict__ ft_b)
{
    __shared__ int   s_idx[CAP];
    __shared__ float s_val[CAP];
    __shared__ int   s_count;
    __shared__ float s_red[8][256];   // per-warp partial sums (8 KB)

    int row  = blockIdx.x;
    int side = blockIdx.y;
    const float* feats = side ? bf : wf;
    const float4* frow = (const float4*)(feats + (size_t)row * FEAT);
    int tid  = threadIdx.x;
    int warp = tid >> 5, lane = tid & 31;

    if (tid == 0) s_count = 0;
    __syncthreads();

    // Coalesced streaming float4 scan: 10240 float4 / 256 threads = 40 iters
#pragma unroll 8
    for (int i = tid; i < FEAT / 4; i += 256) {
        float4 v = ld_stream_f4(&frow[i]);
        if (v.x != 0.f) { int p = atomicAdd(&s_count, 1); if (p < CAP) { s_idx[p] = 4 * i;     s_val[p] = v.x; } }
        if (v.y != 0.f) { int p = atomicAdd(&s_count, 1); if (p < CAP) { s_idx[p] = 4 * i + 1; s_val[p] = v.y; } }
        if (v.z != 0.f) { int p = atomicAdd(&s_count, 1); if (p < CAP) { s_idx[p] = 4 * i + 2; s_val[p] = v.z; } }
        if (v.w != 0.f) { int p = atomicAdd(&s_count, 1); if (p < CAP) { s_idx[p] = 4 * i + 3; s_val[p] = v.w; } }
    }
    __syncthreads();

    int n = min(s_count, CAP);

    // Warp w handles nonzeros k = w, w+8, w+16, ... Each lane accumulates 8
    // h-values (lane*8 .. lane*8+7) in registers.
    float acc[8];
#pragma unroll
    for (int j = 0; j < 8; j++) acc[j] = 0.f;

    for (int k = warp; k < n; k += 8) {
        float v = s_val[k];
        F8 t = ld_table_f8(&g_ftw_t[(size_t)s_idx[k] * H1 + lane * 8]);
#pragma unroll
        for (int j = 0; j < 8; j++) acc[j] = fmaf(v, t.f[j], acc[j]);
    }

    // Stash per-warp partials, reduce across the 8 warps.
#pragma unroll
    for (int j = 0; j < 8; j++) s_red[warp][lane * 8 + j] = acc[j];
    __syncthreads();

    // 256 threads: thread tid reduces h = tid over 8 warps.
    float r = ft_b[tid];
#pragma unroll
    for (int w = 0; w < 8; w++) r += s_red[w][tid];
    r = fminf(fmaxf(r, 0.f), 1.f);
    g_x[(size_t)row * 512 + side * 256 + tid] = r;
}

// ---------------------------------------------------------------------------
// Kernel 3: tail MLP. One warp per batch row, 8 rows per 256-thread block.
// ---------------------------------------------------------------------------
__global__ void __launch_bounds__(256) mlp_kernel(
    const float* __restrict__ fc1_w, const float* __restrict__ fc1_b,
    const float* __restrict__ fc2_w, const float* __restrict__ fc2_b,
    const float* __restrict__ fc3_w, const float* __restrict__ fc3_b,
    float* __restrict__ out)
{
    __shared__ float fc2t[32 * 32];   // transposed: [j][h]
    __shared__ float s_fc3[32];
    int tid = threadIdx.x;

    for (int i = tid; i < 1024; i += 256) {
        int h = i >> 5, j = i & 31;
        fc2t[j * 32 + h] = fc2_w[i];
    }
    if (tid < 32) s_fc3[tid] = fc3_w[tid];
    __syncthreads();

    int warp = tid >> 5, lane = tid & 31;
    int row = blockIdx.x * 8 + warp;

    const float* xr = g_x + (size_t)row * 512;
    float xv[16];
#pragma unroll
    for (int k = 0; k < 16; k++) xv[k] = xr[lane + 32 * k];

    float y1 = 0.f;
#pragma unroll
    for (int h = 0; h < 32; h++) {
        const float* w = fc1_w + h * 512;
        float p = 0.f;
#pragma unroll
        for (int k = 0; k < 16; k++) p = fmaf(__ldg(&w[lane + 32 * k]), xv[k], p);
#pragma unroll
        for (int o = 16; o; o >>= 1) p += __shfl_xor_sync(0xffffffffu, p, o);
        p += fc1_b[h];
        p = fminf(fmaxf(p, 0.f), 1.f);
        if (lane == h) y1 = p;
    }

    float y2 = fc2_b[lane];
#pragma unroll
    for (int j = 0; j < 32; j++) {
        float xj = __shfl_sync(0xffffffffu, y1, j);
        y2 = fmaf(fc2t[j * 32 + lane], xj, y2);
    }
    y2 = fminf(fmaxf(y2, 0.f), 1.f);

    float p3 = s_fc3[lane] * y2;
#pragma unroll
    for (int o = 16; o; o >>= 1) p3 += __shfl_xor_sync(0xffffffffu, p3, o);
    if (lane == 0) out[row] = p3 + fc3_b[0];
}

// ---------------------------------------------------------------------------
extern "C" void kernel_launch(void* const* d_in, const int* in_sizes, int n_in,
                              void* d_out, int out_size) {
    const float* wf    = (const float*)d_in[0];
    const float* bf    = (const float*)d_in[1];
    const float* ft_w  = (const float*)d_in[2];
    const float* ft_b  = (const float*)d_in[3];
    const float* fc1_w = (const float*)d_in[4];
    const float* fc1_b = (const float*)d_in[5];
    const float* fc2_w = (const float*)d_in[6];
    const float* fc2_b = (const float*)d_in[7];
    const float* fc3_w = (const float*)d_in[8];
    const float* fc3_b = (const float*)d_in[9];
    float* out = (float*)d_out;

    dim3 tb(32, 8);
    dim3 tg(FEAT / 32, H1 / 32);
    transpose_kernel<<<tg, tb>>>(ft_w);

    dim3 fg(BATCH, 2);
    ft_kernel<<<fg, 256>>>(wf, bf, ft_b);

    mlp_kernel<<<BATCH / 8, 256>>>(fc1_w, fc1_b, fc2_w, fc2_b, fc3_w, fc3_b, out);
}